// round 14
// baseline (speedup 1.0000x reference)
#include <cuda_runtime.h>
#include <cuda_fp16.h>
#include <cstdint>

#define NB 4
#define NN 4096
#define LOG2E 1.4426950408889634f

// ---------------- scratch (__device__ globals; no allocation) ----------------
__device__ __align__(256) __half g_Qh[NB * NN * 8];   // [b][n][8], pre-scaled by log2e
__device__ __align__(256) __half g_Kh[NB * NN * 8];   // [b][n][8]
__device__ __align__(256) __half g_Vh[NB * NN * 64];  // [b][n][64]

// ---------------- helpers ----------------
__device__ __forceinline__ uint32_t smem_u32(const void* p) {
    uint32_t a;
    asm("{ .reg .u64 t; cvta.to.shared.u64 t, %1; cvt.u32.u64 %0, t; }" : "=r"(a) : "l"(p));
    return a;
}
__device__ __forceinline__ uint32_t swz128(uint32_t b) { return b ^ ((b >> 3) & 0x70u); }

#define CP_ASYNC16(dst, src) \
    asm volatile("cp.async.cg.shared.global [%0], [%1], 16;" :: "r"(dst), "l"(src) : "memory")
#define CP_COMMIT() asm volatile("cp.async.commit_group;" ::: "memory")
#define CP_WAIT0()  asm volatile("cp.async.wait_group 0;" ::: "memory")

#define LDSM_X4(r0, r1, r2, r3, a) \
    asm volatile("ldmatrix.sync.aligned.m8n8.x4.shared.b16 {%0,%1,%2,%3}, [%4];" \
                 : "=r"(r0), "=r"(r1), "=r"(r2), "=r"(r3) : "r"(a))
#define LDSM_X4T(r0, r1, r2, r3, a) \
    asm volatile("ldmatrix.sync.aligned.m8n8.x4.trans.shared.b16 {%0,%1,%2,%3}, [%4];" \
                 : "=r"(r0), "=r"(r1), "=r"(r2), "=r"(r3) : "r"(a))

// S(16x8,f16) = Q(16x8,f16) @ K^T ; C = 0
__device__ __forceinline__ void mma16808h(uint32_t* d, uint32_t a0, uint32_t a1, uint32_t b0) {
    uint32_t z = 0;
    asm volatile("mma.sync.aligned.m16n8k8.row.col.f16.f16.f16.f16 "
                 "{%0,%1}, {%2,%3}, {%4}, {%5,%5};"
                 : "=r"(d[0]), "=r"(d[1]) : "r"(a0), "r"(a1), "r"(b0), "r"(z));
}
// O(16x8,f16) += P(16x16,f16) @ V(16x8,f16)
__device__ __forceinline__ void mma16816h(uint32_t* d, const uint32_t* a, uint32_t b0, uint32_t b1) {
    asm volatile("mma.sync.aligned.m16n8k16.row.col.f16.f16.f16.f16 "
                 "{%0,%1}, {%2,%3,%4,%5}, {%6,%7}, {%0,%1};"
                 : "+r"(d[0]), "+r"(d[1])
                 : "r"(a[0]), "r"(a[1]), "r"(a[2]), "r"(a[3]), "r"(b0), "r"(b1));
}
#define EX2H2(r) asm volatile("ex2.approx.f16x2 %0, %0;" : "+r"(r))
__device__ __forceinline__ uint32_t hadd2u(uint32_t a, uint32_t b) {
    uint32_t d; asm("add.rn.f16x2 %0, %1, %2;" : "=r"(d) : "r"(a), "r"(b)); return d;
}
__device__ __forceinline__ float h2sumf(uint32_t r) {
    __half2 h = *reinterpret_cast<__half2*>(&r);
    return __low2float(h) + __high2float(h);
}

// ---------------------------------------------------------------------------
// Kernel 1: fused QKV projections (f16 outputs, staged coalesced stores)
// ---------------------------------------------------------------------------
__global__ __launch_bounds__(256) void prep_kernel(
    const float* __restrict__ x,
    const float* __restrict__ Wq, const float* __restrict__ bq,
    const float* __restrict__ Wk, const float* __restrict__ bk,
    const float* __restrict__ Wv, const float* __restrict__ bv)
{
    __shared__ __align__(16) float xs[64 * 64];
    __shared__ __align__(16) float ws[80 * 64];   // weights; reused as output staging
    __shared__ float bs[80];

    const int t  = threadIdx.x;
    const int b  = blockIdx.y;
    const int n0 = blockIdx.x * 64;

    for (int lin = t; lin < 80 * 64; lin += 256) {
        int o = lin >> 6, c = lin & 63;
        float w;
        if (o < 8)       w = Wq[o * 64 + c] * LOG2E;
        else if (o < 16) w = Wk[(o - 8) * 64 + c];
        else             w = Wv[(o - 16) * 64 + c];
        ws[o * 64 + c] = w;
    }
    if (t < 80) {
        float bb;
        if (t < 8)       bb = bq[t] * LOG2E;
        else if (t < 16) bb = bk[t - 8];
        else             bb = bv[t - 16];
        bs[t] = bb;
    }
    for (int lin = t; lin < 64 * 64; lin += 256) {
        int c = lin >> 6, i = lin & 63;
        xs[c * 64 + i] = x[(b * 64 + c) * NN + n0 + i];
    }
    __syncthreads();

    const int tx = t & 63;
    const int ty = t >> 6;

    float acc[20];
#pragma unroll
    for (int i = 0; i < 20; i++) acc[i] = 0.f;
#pragma unroll
    for (int c = 0; c < 64; c++) {
        float xv = xs[c * 64 + tx];
#pragma unroll
        for (int oo = 0; oo < 20; oo++)
            acc[oo] += ws[(ty * 20 + oo) * 64 + c] * xv;
    }
    float bias[20];
#pragma unroll
    for (int oo = 0; oo < 20; oo++) bias[oo] = bs[ty * 20 + oo];

    __syncthreads();   // done reading ws -> reuse as staging

    char* stage = (char*)ws;
#pragma unroll
    for (int oo = 0; oo < 20; oo++) {
        int o = ty * 20 + oo;
        __half h = __float2half(acc[oo] + bias[oo]);
        if (o < 8)
            *(__half*)(stage + tx * 16 + o * 2) = h;
        else if (o < 16)
            *(__half*)(stage + 1024 + tx * 16 + (o - 8) * 2) = h;
        else
            *(__half*)(stage + 2048 + tx * 136 + (o - 16) * 2) = h;
    }
    __syncthreads();

    if (t < 64) {
        *(uint4*)(g_Qh + ((size_t)b * NN + n0 + t) * 8) = *(const uint4*)(stage + t * 16);
    } else if (t < 128) {
        int i = t - 64;
        *(uint4*)(g_Kh + ((size_t)b * NN + n0 + i) * 8) = *(const uint4*)(stage + 1024 + i * 16);
    }
#pragma unroll
    for (int i = 0; i < 4; i++) {
        int lin = t + i * 256;               // 1024 chunks of 8B
        int pix = lin >> 4, chk = lin & 15;
        *(uint2*)(g_Vh + ((size_t)b * NN + n0 + pix) * 64 + chk * 4) =
            *(const uint2*)(stage + 2048 + pix * 136 + chk * 8);
    }
}

// ---------------------------------------------------------------------------
// Kernel 2: flash attention, all-f16 mma.sync, 3 CTAs/SM (84-reg budget).
// CTA = 64 queries, 8 warps: rowgrp = w>>2 (32 rows), kq = w&3 (32-key quarter
// of each 128-key tile). 2-stage cp.async, one barrier/iter, sequential
// 16-key chunks (minimal live regs); P register-chained into MMA2.
// ---------------------------------------------------------------------------
#define SM_K0 0u
#define SM_K1 2048u
#define SM_V0 4096u
#define SM_V1 20480u
#define SM_L  32768u      // epilogue: float[4][64]
#define U_BYTES 36864

__global__ __launch_bounds__(256, 3) void attn_kernel(
    const float* __restrict__ x,
    const float* __restrict__ gamma_p,
    float* __restrict__ out)
{
    __shared__ __align__(128) __half sQ[64 * 8];
    __shared__ __align__(1024) unsigned char U[U_BYTES];

    const int t      = threadIdx.x;
    const int lane   = t & 31;
    const int w      = t >> 5;
    const int rowgrp = w >> 2;          // 0,1 -> rows [32*rowgrp, +32)
    const int kq     = w & 3;           // key quarter within each 128-key tile
    const int b      = blockIdx.y;
    const int q0     = blockIdx.x * 64;

    const uint32_t sbQ = smem_u32(sQ);
    const uint32_t sbU = smem_u32(U);

    // PDL: wait for prep_kernel before touching its outputs
    cudaGridDependencySynchronize();

    // initial loads: Q + tile 0
    if (t < 64)
        CP_ASYNC16(sbQ + (uint32_t)t * 16u, (const char*)(g_Qh + ((size_t)b * NN + q0 + t) * 8));
    if (t < 128)
        CP_ASYNC16(sbU + SM_K0 + (uint32_t)t * 16u, (const char*)(g_Kh + ((size_t)b * NN + t) * 8));
#pragma unroll
    for (int i = 0; i < 4; i++) {
        int cid = t + i * 256;                  // 1024 chunks: key = cid>>3, chk = cid&7
        int vk = cid >> 3, vc = cid & 7;
        CP_ASYNC16(sbU + SM_V0 + swz128((uint32_t)vk * 128u + (uint32_t)vc * 16u),
                   (const char*)(g_Vh + ((size_t)b * NN + vk) * 64 + vc * 8));
    }
    CP_COMMIT();

    uint32_t o[2][16];                          // [rowfrag][nt*2+d] f16x2 accumulators
#pragma unroll
    for (int rf = 0; rf < 2; rf++)
#pragma unroll
        for (int i = 0; i < 16; i++) o[rf][i] = 0u;
    float lacc[4] = {0.f, 0.f, 0.f, 0.f};       // row sums: [rf*2+d]
    uint32_t qa[4];

    CP_WAIT0();
    __syncthreads();
    LDSM_X4(qa[0], qa[1], qa[2], qa[3], sbQ + (uint32_t)(rowgrp * 32 + lane) * 16u);

    for (int it = 0; it < 32; it++) {
        if (it + 1 < 32) {      // prefetch next tile into other buffer
            const int nb = (it + 1) & 1;
            const uint32_t kdst = sbU + (nb ? SM_K1 : SM_K0);
            const uint32_t vdst = sbU + (nb ? SM_V1 : SM_V0);
            const int kbase = (it + 1) * 128;
            if (t < 128)
                CP_ASYNC16(kdst + (uint32_t)t * 16u,
                           (const char*)(g_Kh + ((size_t)b * NN + kbase + t) * 8));
#pragma unroll
            for (int i = 0; i < 4; i++) {
                int cid = t + i * 256;
                int vk = cid >> 3, vc = cid & 7;
                CP_ASYNC16(vdst + swz128((uint32_t)vk * 128u + (uint32_t)vc * 16u),
                           (const char*)(g_Vh + ((size_t)b * NN + kbase + vk) * 64 + vc * 8));
            }
            CP_COMMIT();
        }

        const uint32_t kbuf = sbU + ((it & 1) ? SM_K1 : SM_K0);
        const uint32_t vbuf = sbU + ((it & 1) ? SM_V1 : SM_V0);

        uint32_t kb[4];     // this warp's 32-key quarter
        LDSM_X4(kb[0], kb[1], kb[2], kb[3], kbuf + (uint32_t)(kq * 32 + lane) * 16u);

#pragma unroll
        for (int m = 0; m < 2; m++) {   // sequential 16-key chunks (low live regs)
            uint32_t p[8];              // S -> P for both rowfrags
            mma16808h(p + 0, qa[0], qa[1], kb[2 * m]);
            mma16808h(p + 2, qa[0], qa[1], kb[2 * m + 1]);
            mma16808h(p + 4, qa[2], qa[3], kb[2 * m]);
            mma16808h(p + 6, qa[2], qa[3], kb[2 * m + 1]);

            EX2H2(p[0]); EX2H2(p[1]); EX2H2(p[2]); EX2H2(p[3]);
            EX2H2(p[4]); EX2H2(p[5]); EX2H2(p[6]); EX2H2(p[7]);

            lacc[0] += h2sumf(hadd2u(p[0], p[2]));
            lacc[1] += h2sumf(hadd2u(p[1], p[3]));
            lacc[2] += h2sumf(hadd2u(p[4], p[6]));
            lacc[3] += h2sumf(hadd2u(p[5], p[7]));

            uint32_t vb[16];
            const uint32_t vkey = (uint32_t)(kq * 32 + m * 16 + ((lane >> 3) & 1) * 8 + (lane & 7));
#pragma unroll
            for (int ntp = 0; ntp < 4; ntp++) {
                uint32_t cb = (uint32_t)(ntp * 2 + (lane >> 4));
                LDSM_X4T(vb[4 * ntp], vb[4 * ntp + 1], vb[4 * ntp + 2], vb[4 * ntp + 3],
                         vbuf + swz128(vkey * 128u + cb * 16u));
            }
#pragma unroll
            for (int nt = 0; nt < 8; nt++) {
                mma16816h(&o[0][2 * nt], p + 0, vb[2 * nt], vb[2 * nt + 1]);
                mma16816h(&o[1][2 * nt], p + 4, vb[2 * nt], vb[2 * nt + 1]);
            }
        }

        if (it + 1 < 32) {
            CP_WAIT0();
            __syncthreads();    // next tile visible; everyone done with its buffer
        }
    }

    // ---- epilogue: combine 4 key-quarters through smem ----
#pragma unroll
    for (int j = 0; j < 4; j++) {
        lacc[j] += __shfl_xor_sync(0xffffffffu, lacc[j], 1);
        lacc[j] += __shfl_xor_sync(0xffffffffu, lacc[j], 2);
    }
    const float gma = __ldg(gamma_p);

    __syncthreads();            // all loop reads of U done

    __half* sOp = (__half*)U;               // [kq][ch 64][q 64] f16 partials (32KB)
    float*  sL  = (float*)(U + SM_L);       // [kq][64] partial row sums

    if ((lane & 3) == 0) {
#pragma unroll
        for (int j = 0; j < 4; j++) {       // j = rf*2 + d -> row offset rf*16 + d*8
            int row = rowgrp * 32 + (j >> 1) * 16 + (j & 1) * 8 + (lane >> 2);
            sL[kq * 64 + row] = lacc[j];
        }
    }
#pragma unroll
    for (int rf = 0; rf < 2; rf++)
#pragma unroll
        for (int nt = 0; nt < 8; nt++)
#pragma unroll
            for (int d = 0; d < 2; d++) {
                __half2 hv = *reinterpret_cast<__half2*>(&o[rf][nt * 2 + d]);
                int row = rowgrp * 32 + rf * 16 + d * 8 + (lane >> 2);
                int c0  = nt * 8 + (lane & 3) * 2;
                sOp[(kq * 64 + c0) * 64 + row]     = __low2half(hv);
                sOp[(kq * 64 + c0 + 1) * 64 + row] = __high2half(hv);
            }
    __syncthreads();

    // final: thread owns q = t&63, channels (t>>6) + 4*i
    {
        const int q = t & 63;
        const float l = sL[q] + sL[64 + q] + sL[128 + q] + sL[192 + q];
        const float inv = gma / l;
#pragma unroll
        for (int i = 0; i < 16; i++) {
            int c = (t >> 6) + 4 * i;
            float acc = (float)sOp[(0 * 64 + c) * 64 + q] + (float)sOp[(1 * 64 + c) * 64 + q]
                      + (float)sOp[(2 * 64 + c) * 64 + q] + (float)sOp[(3 * 64 + c) * 64 + q];
            size_t idx = ((size_t)b * 64 + c) * NN + q0 + q;
            out[idx] = acc * inv + x[idx];
        }
    }
}

// ---------------------------------------------------------------------------
extern "C" void kernel_launch(void* const* d_in, const int* in_sizes, int n_in,
                              void* d_out, int out_size) {
    (void)in_sizes; (void)n_in; (void)out_size;
    const float* x     = (const float*)d_in[0];
    const float* Wq    = (const float*)d_in[1];
    const float* bq    = (const float*)d_in[2];
    const float* Wk    = (const float*)d_in[3];
    const float* bk    = (const float*)d_in[4];
    const float* Wv    = (const float*)d_in[5];
    const float* bv    = (const float*)d_in[6];
    const float* gamma = (const float*)d_in[7];
    float* out = (float*)d_out;

    prep_kernel<<<dim3(64, NB), 256>>>(x, Wq, bq, Wk, bk, Wv, bv);

    // attn with programmatic stream serialization
    cudaLaunchConfig_t cfg = {};
    cfg.gridDim  = dim3(64, NB);
    cfg.blockDim = dim3(256);
    cfg.dynamicSmemBytes = 0;
    cfg.stream = 0;
    cudaLaunchAttribute attrs[1];
    attrs[0].id = cudaLaunchAttributeProgrammaticStreamSerialization;
    attrs[0].val.programmaticStreamSerializationAllowed = 1;
    cfg.attrs = attrs;
    cfg.numAttrs = 1;
    cudaLaunchKernelEx(&cfg, attn_kernel, x, gamma, out);
}